// round 9
// baseline (speedup 1.0000x reference)
#include <cuda_runtime.h>
#include <cuda_fp16.h>
#include <cstdint>

// dw[p][q] = LR * ( (1/B)*sum_b post[b][p]*pre[b][q] - WD*W[p][q] )
// B=128, P=Q=1024.  fp16 single-pass mma.sync (rel err ~3e-5).
// R9: K-split 2-stage pipeline: cp.async group0 (k0-63) / group1 (k64-127);
// convert0 -> MMA(ks 0-3) overlaps group1 arrival -> convert1 -> MMA(ks 4-7).
// W prefetch issued first (DRAM-cold). float2->half2 packed conversion.

#define DIM      1024
#define KDIM     128
#define NTHREADS 512
#define BM       128
#define BN       64
#define LDA      136                 // fp16/row pitch (272B), ldmatrix conflict-free

// SMEM byte offsets
#define RAW_A    0                   // 128k x 128m fp32 = 65536 (512B rows)
#define RAW_B    65536               // 128k x  64m fp32 = 32768 (256B rows)
#define FA_OFF   98304               // fp16 A tile, 34816
#define FB_OFF   133120              // fp16 B tile, 17408
#define SMEM_TOTAL 150528

static __device__ __forceinline__ uint32_t smem_u32(const void* p) {
    uint32_t a;
    asm("{ .reg .u64 t; cvta.to.shared.u64 t, %1; cvt.u32.u64 %0, t; }" : "=r"(a) : "l"(p));
    return a;
}
static __device__ __forceinline__ void cp16(uint32_t saddr, const void* gaddr) {
    asm volatile("cp.async.ca.shared.global [%0], [%1], 16;" :: "r"(saddr), "l"(gaddr));
}
static __device__ __forceinline__ void ldsm_x4(uint32_t* r, uint32_t addr) {
    asm volatile("ldmatrix.sync.aligned.m8n8.x4.shared.b16 {%0,%1,%2,%3}, [%4];"
                 : "=r"(r[0]), "=r"(r[1]), "=r"(r[2]), "=r"(r[3]) : "r"(addr));
}
static __device__ __forceinline__ void mma16816(float* c, const uint32_t* a,
                                                uint32_t b0, uint32_t b1) {
    asm volatile(
        "mma.sync.aligned.m16n8k16.row.col.f32.f16.f16.f32 "
        "{%0,%1,%2,%3}, {%4,%5,%6,%7}, {%8,%9}, {%0,%1,%2,%3};"
        : "+f"(c[0]), "+f"(c[1]), "+f"(c[2]), "+f"(c[3])
        : "r"(a[0]), "r"(a[1]), "r"(a[2]), "r"(a[3]), "r"(b0), "r"(b1));
}
static __device__ __forceinline__ uint32_t pack_h2(float a, float b) {
    const __half2 h = __floats2half2_rn(a, b);   // one F2FP: a in low, b in high
    return *(const uint32_t*)&h;
}

// Convert one K-half of raw fp32 SMEM [k][m] -> fp16 SMEM [m][k] (LDA pitch).
// ROWS = m extent; RAWPITCH = ROWS*4 bytes per k-row.
template <int ROWS>
static __device__ __forceinline__ void convert_half(const char* raw, char* dst,
                                                    int half, int tid) {
    #pragma unroll
    for (int it = 0; it < ROWS * 8 / NTHREADS; ++it) {
        const int u  = tid + NTHREADS * it;
        const int m  = u & (ROWS - 1);
        const int kg = half * 8 + (u / ROWS);    // 8-k group
        float v[8];
        #pragma unroll
        for (int j = 0; j < 8; ++j)
            v[j] = *(const float*)(raw + (kg * 8 + j) * (ROWS * 4) + m * 4);
        uint4 o;
        o.x = pack_h2(v[0], v[1]); o.y = pack_h2(v[2], v[3]);
        o.z = pack_h2(v[4], v[5]); o.w = pack_h2(v[6], v[7]);
        *(uint4*)(dst + (m * LDA + kg * 8) * 2) = o;
    }
}

__global__ __launch_bounds__(NTHREADS, 1)
void hebbian_fp16_kernel(const float* __restrict__ pre,
                         const float* __restrict__ post,
                         const float* __restrict__ W,
                         float* __restrict__ out)
{
    extern __shared__ char smem[];
    const uint32_t sbase = smem_u32(smem);
    const int tid  = threadIdx.x;
    const int lane = tid & 31;
    const int wid  = tid >> 5;
    const int pm0  = blockIdx.y * BM;
    const int qn0  = blockIdx.x * BN;

    // ---- warp tiling: 8(m) x 2(n) warps, warp tile m16 x n32 ----
    const int wm = (wid >> 1) * 16;
    const int wn = (wid & 1) * 32;
    const int prow = pm0 + wm + (lane >> 2);
    const int qcol = qn0 + wn + (lane & 3) * 2;

    // ---- W prefetch FIRST (DRAM-cold, longest latency) ----
    float2 wv[4][2];
    #pragma unroll
    for (int nn = 0; nn < 4; ++nn) {
        const int q = qcol + nn * 8;
        wv[nn][0] = *(const float2*)(W + (size_t)prow * DIM + q);
        wv[nn][1] = *(const float2*)(W + (size_t)(prow + 8) * DIM + q);
    }

    // ---- cp.async: group0 = k[0,64) of A+B, group1 = k[64,128) ----
    #pragma unroll
    for (int h = 0; h < 2; ++h) {
        #pragma unroll
        for (int it = 0; it < 4; ++it) {                 // A half: 2048 chunks
            const int c = tid + NTHREADS * it;
            const int k = h * 64 + (c >> 5);
            const int f = (c & 31) * 4;
            cp16(sbase + RAW_A + k * 512 + f * 4, post + (size_t)k * DIM + pm0 + f);
        }
        #pragma unroll
        for (int it = 0; it < 2; ++it) {                 // B half: 1024 chunks
            const int c = tid + NTHREADS * it;
            const int k = h * 64 + (c >> 4);
            const int f = (c & 15) * 4;
            cp16(sbase + RAW_B + k * 256 + f * 4, pre + (size_t)k * DIM + qn0 + f);
        }
        asm volatile("cp.async.commit_group;" ::: "memory");
    }

    float acc[4][4];
    #pragma unroll
    for (int j = 0; j < 4; ++j)
        #pragma unroll
        for (int r = 0; r < 4; ++r)
            acc[j][r] = 0.0f;

    const int frow = lane & 15;
    const int fcol = (lane >> 4) * 8;

    // ================= stage 0: convert + MMA on k[0,64) =================
    asm volatile("cp.async.wait_group 1;" ::: "memory");
    __syncthreads();
    convert_half<BM>(smem + RAW_A, smem + FA_OFF, 0, tid);
    convert_half<BN>(smem + RAW_B, smem + FB_OFF, 0, tid);
    __syncthreads();

    #pragma unroll
    for (int ks = 0; ks < 4; ++ks) {
        const int kb = ks * 16 + fcol;
        uint32_t a[4], b[2][4];
        ldsm_x4(a, sbase + FA_OFF + ((wm + frow) * LDA + kb) * 2);
        #pragma unroll
        for (int nb = 0; nb < 2; ++nb)
            ldsm_x4(b[nb], sbase + FB_OFF + ((wn + nb * 16 + frow) * LDA + kb) * 2);
        #pragma unroll
        for (int nn = 0; nn < 4; ++nn) {
            const int nb = nn >> 1, sel = nn & 1;
            mma16816(acc[nn], a, b[nb][sel], b[nb][sel + 2]);
        }
    }

    // ================= stage 1: convert + MMA on k[64,128) ================
    asm volatile("cp.async.wait_group 0;" ::: "memory");
    convert_half<BM>(smem + RAW_A, smem + FA_OFF, 1, tid);
    convert_half<BN>(smem + RAW_B, smem + FB_OFF, 1, tid);
    __syncthreads();

    #pragma unroll
    for (int ks = 4; ks < 8; ++ks) {
        const int kb = ks * 16 + fcol;
        uint32_t a[4], b[2][4];
        ldsm_x4(a, sbase + FA_OFF + ((wm + frow) * LDA + kb) * 2);
        #pragma unroll
        for (int nb = 0; nb < 2; ++nb)
            ldsm_x4(b[nb], sbase + FB_OFF + ((wn + nb * 16 + frow) * LDA + kb) * 2);
        #pragma unroll
        for (int nn = 0; nn < 4; ++nn) {
            const int nb = nn >> 1, sel = nn & 1;
            mma16816(acc[nn], a, b[nb][sel], b[nb][sel + 2]);
        }
    }

    // ---- fused epilogue: dw = acc*(LR/B) - (LR*WD)*W (W already in regs) ----
    const float c1 = 0.005f / 128.0f;
    const float c2 = 0.005f * 0.0001f;
    #pragma unroll
    for (int nn = 0; nn < 4; ++nn) {
        const int q = qcol + nn * 8;
        #pragma unroll
        for (int h = 0; h < 2; ++h) {
            const int p = prow + h * 8;
            float2 o;
            o.x = fmaf(acc[nn][2 * h + 0], c1, -c2 * wv[nn][h].x);
            o.y = fmaf(acc[nn][2 * h + 1], c1, -c2 * wv[nn][h].y);
            *(float2*)(out + (size_t)p * DIM + q) = o;
        }
    }
}

extern "C" void kernel_launch(void* const* d_in, const int* in_sizes, int n_in,
                              void* d_out, int out_size)
{
    const float* pre  = (const float*)d_in[0];   // (128, 1024)
    const float* post = (const float*)d_in[1];   // (128, 1024)
    const float* W    = (const float*)d_in[2];   // (1024, 1024)
    float* out = (float*)d_out;                  // (1024, 1024)

    static bool attr_set = false;
    if (!attr_set) {
        cudaFuncSetAttribute(hebbian_fp16_kernel,
                             cudaFuncAttributeMaxDynamicSharedMemorySize, SMEM_TOTAL);
        attr_set = true;
    }
    dim3 grid(DIM / BN, DIM / BM);   // (16, 8) = 128 CTAs, 1/SM, single wave
    hebbian_fp16_kernel<<<grid, NTHREADS, SMEM_TOTAL>>>(pre, post, W, out);
}

// round 10
// speedup vs baseline: 1.0295x; 1.0295x over previous
#include <cuda_runtime.h>
#include <cuda_fp16.h>
#include <cstdint>

// dw[p][q] = LR * ( (1/B)*sum_b post[b][p]*pre[b][q] - WD*W[p][q] )
// B=128, P=Q=1024.  fp16 single-pass mma.sync (rel err ~3e-5).
// R10: kernel1 streams fp32->fp16 (same [b][m] layout, fully coalesced).
// kernel2 cp.asyncs fp16 [k][m] tiles and feeds mma via ldmatrix.x4.trans —
// no conversion, no transpose inside the GEMM. Halved L2 operand traffic.

#define DIM      1024
#define KDIM     128
#define NTHREADS 512
#define BM       128
#define BN       64

#define PA       272                  // A tile row pitch bytes (256 data + 16 pad)
#define PB       144                  // B tile row pitch bytes (128 data + 16 pad)
#define FA       0
#define FB       (KDIM * PA)          // 34816
#define SMEM_TOTAL (FB + KDIM * PB)   // 53248

__device__ __align__(16) __half g_postH[KDIM * DIM];
__device__ __align__(16) __half g_preH [KDIM * DIM];

static __device__ __forceinline__ uint32_t smem_u32(const void* p) {
    uint32_t a;
    asm("{ .reg .u64 t; cvta.to.shared.u64 t, %1; cvt.u32.u64 %0, t; }" : "=r"(a) : "l"(p));
    return a;
}
static __device__ __forceinline__ void cp16(uint32_t saddr, const void* gaddr) {
    asm volatile("cp.async.ca.shared.global [%0], [%1], 16;" :: "r"(saddr), "l"(gaddr));
}
static __device__ __forceinline__ void ldsm_x4_trans(uint32_t* r, uint32_t addr) {
    asm volatile("ldmatrix.sync.aligned.m8n8.x4.trans.shared.b16 {%0,%1,%2,%3}, [%4];"
                 : "=r"(r[0]), "=r"(r[1]), "=r"(r[2]), "=r"(r[3]) : "r"(addr));
}
static __device__ __forceinline__ void mma16816(float* c, const uint32_t* a,
                                                uint32_t b0, uint32_t b1) {
    asm volatile(
        "mma.sync.aligned.m16n8k16.row.col.f32.f16.f16.f32 "
        "{%0,%1,%2,%3}, {%4,%5,%6,%7}, {%8,%9}, {%0,%1,%2,%3};"
        : "+f"(c[0]), "+f"(c[1]), "+f"(c[2]), "+f"(c[3])
        : "r"(a[0]), "r"(a[1]), "r"(a[2]), "r"(a[3]), "r"(b0), "r"(b1));
}
static __device__ __forceinline__ uint32_t pack_h2(float a, float b) {
    const __half2 h = __floats2half2_rn(a, b);
    return *(const uint32_t*)&h;
}

// ---------------- kernel 1: streaming fp32 -> fp16 (layout-preserving) ----------------
__global__ __launch_bounds__(256, 4)
void convert_kernel(const float* __restrict__ pre, const float* __restrict__ post)
{
    const int n = KDIM * DIM / 8;                 // 16384 8-float units per tensor
    const int u = blockIdx.x * 256 + threadIdx.x; // 32768 total
    const bool isPost = (u >= n);
    const float4* src = (const float4*)(isPost ? post : pre);
    __half* dst = isPost ? g_postH : g_preH;
    const int i = isPost ? (u - n) : u;
    const float4 v0 = src[i * 2];
    const float4 v1 = src[i * 2 + 1];
    uint4 o;
    o.x = pack_h2(v0.x, v0.y); o.y = pack_h2(v0.z, v0.w);
    o.z = pack_h2(v1.x, v1.y); o.w = pack_h2(v1.z, v1.w);
    ((uint4*)dst)[i] = o;
}

// ---------------- kernel 2: GEMM (fp16 in, ldmatrix.trans, fused epilogue) ------------
__global__ __launch_bounds__(NTHREADS, 1)
void hebbian_gemm_kernel(const float* __restrict__ W, float* __restrict__ out)
{
    extern __shared__ char smem[];
    const uint32_t sbase = smem_u32(smem);
    const int tid  = threadIdx.x;
    const int lane = tid & 31;
    const int wid  = tid >> 5;
    const int pm0  = blockIdx.y * BM;
    const int qn0  = blockIdx.x * BN;

    // warp tiling: 8(m) x 2(n), warp tile m16 x n32
    const int wm = (wid >> 1) * 16;
    const int wn = (wid & 1) * 32;
    const int prow = pm0 + wm + (lane >> 2);
    const int qcol = qn0 + wn + (lane & 3) * 2;

    // ---- W prefetch first (longest latency) ----
    float2 wv[4][2];
    #pragma unroll
    for (int nn = 0; nn < 4; ++nn) {
        const int q = qcol + nn * 8;
        wv[nn][0] = *(const float2*)(W + (size_t)prow * DIM + q);
        wv[nn][1] = *(const float2*)(W + (size_t)(prow + 8) * DIM + q);
    }

    // ---- cp.async fp16 [k][m] tiles straight into smem (no transform) ----
    #pragma unroll
    for (int it = 0; it < 4; ++it) {              // A: 128 rows x 16 chunks = 2048
        const int c = tid + NTHREADS * it;
        const int k = c >> 4;
        const int f = (c & 15);
        cp16(sbase + FA + k * PA + f * 16, g_postH + (size_t)k * DIM + pm0 + f * 8);
    }
    #pragma unroll
    for (int it = 0; it < 2; ++it) {              // B: 128 rows x 8 chunks = 1024
        const int c = tid + NTHREADS * it;
        const int k = c >> 3;
        const int f = (c & 7);
        cp16(sbase + FB + k * PB + f * 16, g_preH + (size_t)k * DIM + qn0 + f * 8);
    }
    asm volatile("cp.async.commit_group;\n\tcp.async.wait_group 0;" ::: "memory");
    __syncthreads();

    float acc[4][4];
    #pragma unroll
    for (int j = 0; j < 4; ++j)
        #pragma unroll
        for (int r = 0; r < 4; ++r)
            acc[j][r] = 0.0f;

    // trans-ldmatrix lane addressing: 8x8 tiles T0..T3 in (m-then-k) order,
    // identical tile->register assignment as the verified non-trans scheme.
    const int kl = (lane & 7) + ((lane >> 4) << 3);   // k row within 16-block
    const int ml = (lane & 8);                        // m/n sub-tile (0 or 8)

    #pragma unroll
    for (int ks = 0; ks < KDIM / 16; ++ks) {
        const int kb = ks * 16;
        uint32_t a[4], b[2][4];
        ldsm_x4_trans(a, sbase + FA + (kb + kl) * PA + (wm + ml) * 2);
        #pragma unroll
        for (int nb = 0; nb < 2; ++nb)
            ldsm_x4_trans(b[nb], sbase + FB + (kb + kl) * PB + (wn + nb * 16 + ml) * 2);
        #pragma unroll
        for (int nn = 0; nn < 4; ++nn) {
            const int nb = nn >> 1, sel = nn & 1;
            mma16816(acc[nn], a, b[nb][sel], b[nb][sel + 2]);
        }
    }

    // ---- fused epilogue: dw = acc*(LR/B) - (LR*WD)*W ----
    const float c1 = 0.005f / 128.0f;
    const float c2 = 0.005f * 0.0001f;
    #pragma unroll
    for (int nn = 0; nn < 4; ++nn) {
        const int q = qcol + nn * 8;
        #pragma unroll
        for (int h = 0; h < 2; ++h) {
            const int p = prow + h * 8;
            float2 o;
            o.x = fmaf(acc[nn][2 * h + 0], c1, -c2 * wv[nn][h].x);
            o.y = fmaf(acc[nn][2 * h + 1], c1, -c2 * wv[nn][h].y);
            *(float2*)(out + (size_t)p * DIM + q) = o;
        }
    }
}

extern "C" void kernel_launch(void* const* d_in, const int* in_sizes, int n_in,
                              void* d_out, int out_size)
{
    const float* pre  = (const float*)d_in[0];   // (128, 1024)
    const float* post = (const float*)d_in[1];   // (128, 1024)
    const float* W    = (const float*)d_in[2];   // (1024, 1024)
    float* out = (float*)d_out;                  // (1024, 1024)

    static bool attr_set = false;
    if (!attr_set) {
        cudaFuncSetAttribute(hebbian_gemm_kernel,
                             cudaFuncAttributeMaxDynamicSharedMemorySize, SMEM_TOTAL);
        attr_set = true;
    }

    convert_kernel<<<128, 256>>>(pre, post);

    dim3 grid(DIM / BN, DIM / BM);   // (16, 8) = 128 CTAs, 1/SM
    hebbian_gemm_kernel<<<grid, NTHREADS, SMEM_TOTAL>>>(W, out);
}